// round 16
// baseline (speedup 1.0000x reference)
#include <cuda_runtime.h>
#include <cuda_bf16.h>
#include <math.h>
#include <stdint.h>

// Problem constants
#define HID   1024
#define NH    16
#define HD    64
#define MROWS 16384           // B*S = 2*8192
#define OUT_ELEMS (MROWS * HID)
#define M_ELEMS   (NH * HD * HD)
#define Z_ELEMS   (NH * HD)
#define NCHUNK 32

typedef unsigned long long u64;
typedef unsigned int u32;

// Scratch (no cudaMalloc -> device globals)
__device__ float g_q[MROWS * HID];
__device__ float g_k[MROWS * HID];
__device__ float g_v[MROWS * HID];
__device__ float g_W2[HID * HID];
__device__ float g_Mpart[NCHUNK * NH * HD * HD];
__device__ float g_zpart[NCHUNK * Z_ELEMS];
// bf16-split operands
__device__ __nv_bfloat16 g_Ahi[MROWS * HID];
__device__ __nv_bfloat16 g_Alo[MROWS * HID];
__device__ __nv_bfloat16 g_Wkhi[HID * HID], g_Wklo[HID * HID];   // transposed [n][k]
__device__ __nv_bfloat16 g_Wvhi[HID * HID], g_Wvlo[HID * HID];
__device__ __nv_bfloat16 g_W2hi[HID * HID], g_W2lo[HID * HID];

// ---------------------------------------------------------------------------
// f32x2 packed-FMA helpers (bit-exact FFMA.rn lanes) — q path only
// ---------------------------------------------------------------------------
__device__ __forceinline__ u64 pack_dup(float a) {
    u64 r; asm("mov.b64 %0, {%1, %1};" : "=l"(r) : "f"(a)); return r;
}
__device__ __forceinline__ void ffma2(u64& d, u64 a, u64 b) {
    asm("fma.rn.f32x2 %0, %1, %2, %0;" : "+l"(d) : "l"(a), "l"(b));
}
__device__ __forceinline__ void unpack2(u64 v, float& lo, float& hi) {
    asm("mov.b64 {%0, %1}, %2;" : "=f"(lo), "=f"(hi) : "l"(v));
}

// Warp-level bf16 MMA (sm_80+ feature; plain sm_103 PTX target OK)
__device__ __forceinline__ void mma16816(float* d, const u32* a, u32 b0, u32 b1) {
    asm volatile(
        "mma.sync.aligned.m16n8k16.row.col.f32.bf16.bf16.f32 "
        "{%0,%1,%2,%3}, {%4,%5,%6,%7}, {%8,%9}, {%0,%1,%2,%3};"
        : "+f"(d[0]), "+f"(d[1]), "+f"(d[2]), "+f"(d[3])
        : "r"(a[0]), "r"(a[1]), "r"(a[2]), "r"(a[3]), "r"(b0), "r"(b1));
}

// ---------------------------------------------------------------------------
// Kernel 1: W2[h*64+d, n] = sum_e M[h,d,e] * Wo[h*64+e, n]   (fp32)
// ---------------------------------------------------------------------------
__global__ void build_w2_kernel(const float* __restrict__ Mm,
                                const float* __restrict__ Wo) {
    __shared__ float Ms[64][64];
    __shared__ float Ws[64][64];
    const int h  = blockIdx.y;
    const int nb = blockIdx.x * 64;
    const int tid = threadIdx.x;

    for (int i = tid; i < 4096; i += 256)
        Ms[i >> 6][i & 63] = Mm[h * 4096 + i];
    for (int i = tid; i < 4096; i += 256)
        Ws[i >> 6][i & 63] = Wo[(size_t)(h * 64 + (i >> 6)) * HID + nb + (i & 63)];
    __syncthreads();

    const int nn = tid & 63;
    const int dg = tid >> 6;
    for (int d = dg; d < 64; d += 4) {
        float s = 0.f;
        #pragma unroll 16
        for (int e = 0; e < 64; e++) s += Ms[d][e] * Ws[e][nn];
        g_W2[(size_t)(h * 64 + d) * HID + nb + nn] = s;
    }
}

// ---------------------------------------------------------------------------
// fp32 -> (hi, lo) bf16 split. src==null -> read g_q.
// ---------------------------------------------------------------------------
__global__ __launch_bounds__(256)
void split_kernel(const float* __restrict__ src) {
    const float* s = src ? src : (const float*)g_q;
    int i = blockIdx.x * 256 + threadIdx.x;     // float4 index
    float4 v = ((const float4*)s)[i];
    __nv_bfloat16 h0 = __float2bfloat16_rn(v.x);
    __nv_bfloat16 h1 = __float2bfloat16_rn(v.y);
    __nv_bfloat16 h2 = __float2bfloat16_rn(v.z);
    __nv_bfloat16 h3 = __float2bfloat16_rn(v.w);
    __nv_bfloat16 l0 = __float2bfloat16_rn(v.x - __bfloat162float(h0));
    __nv_bfloat16 l1 = __float2bfloat16_rn(v.y - __bfloat162float(h1));
    __nv_bfloat16 l2 = __float2bfloat16_rn(v.z - __bfloat162float(h2));
    __nv_bfloat16 l3 = __float2bfloat16_rn(v.w - __bfloat162float(h3));
    u32 hA = (u32)__bfloat16_as_ushort(h0) | ((u32)__bfloat16_as_ushort(h1) << 16);
    u32 hB = (u32)__bfloat16_as_ushort(h2) | ((u32)__bfloat16_as_ushort(h3) << 16);
    u32 lA = (u32)__bfloat16_as_ushort(l0) | ((u32)__bfloat16_as_ushort(l1) << 16);
    u32 lB = (u32)__bfloat16_as_ushort(l2) | ((u32)__bfloat16_as_ushort(l3) << 16);
    ((uint2*)g_Ahi)[i] = make_uint2(hA, hB);
    ((uint2*)g_Alo)[i] = make_uint2(lA, lB);
}

// ---------------------------------------------------------------------------
// Weight W [k][n] fp32 -> transposed bf16 split [n][k]. which: 0=Wk 1=Wv 2=g_W2
// ---------------------------------------------------------------------------
__global__ __launch_bounds__(256)
void conv_w_kernel(const float* __restrict__ src, int which) {
    __shared__ float t[32][33];
    const float* W = src ? src : (const float*)g_W2;
    __nv_bfloat16* Thi = (which == 0) ? g_Wkhi : (which == 1) ? g_Wvhi : g_W2hi;
    __nv_bfloat16* Tlo = (which == 0) ? g_Wklo : (which == 1) ? g_Wvlo : g_W2lo;

    const int k0 = blockIdx.x * 32;
    const int n0 = blockIdx.y * 32;
    const int r  = threadIdx.x >> 5;
    const int c  = threadIdx.x & 31;

    #pragma unroll
    for (int i = 0; i < 4; i++) {
        int rr = r + i * 8;
        t[rr][c] = W[(size_t)(k0 + rr) * HID + n0 + c];
    }
    __syncthreads();
    #pragma unroll
    for (int i = 0; i < 4; i++) {
        int rr = r + i * 8;
        float v = t[c][rr];            // = W[k0+c][n0+rr]
        __nv_bfloat16 hi = __float2bfloat16_rn(v);
        __nv_bfloat16 lo = __float2bfloat16_rn(v - __bfloat162float(hi));
        Thi[(size_t)(n0 + rr) * HID + k0 + c] = hi;
        Tlo[(size_t)(n0 + rr) * HID + k0 + c] = lo;
    }
}

// ---------------------------------------------------------------------------
// mma core (device fn): D[128x128] = A[128x1024] x Bt[128x1024]^T, bf16-split
// 3 terms, fp32 acc. 8 warps (4Mx2N), warp tile 32x64, BK=32, reg prefetch.
// Uses caller-provided 40KB shared region.
// ---------------------------------------------------------------------------
#define LDP 40   // padded smem row length (bf16): 32 + 8
#define SM_BYTES 40960

__device__ __forceinline__
void mma_core(char* smraw,
              const __nv_bfloat16* __restrict__ Bhi,
              const __nv_bfloat16* __restrict__ Blo,
              float* __restrict__ Out, const float* __restrict__ Bias,
              int bm, int bn) {
    typedef __nv_bfloat16 Row[LDP];
    Row* sAhi = (Row*)(smraw);
    Row* sAlo = (Row*)(smraw + 10240);
    Row* sBhi = (Row*)(smraw + 20480);
    Row* sBlo = (Row*)(smraw + 30720);

    const __nv_bfloat16* Ahi = g_Ahi;
    const __nv_bfloat16* Alo = g_Alo;

    const int tid  = threadIdx.x;
    const int wid  = tid >> 5;
    const int lane = tid & 31;
    const int wm = wid & 3;
    const int wn = wid >> 2;
    const int grp = lane >> 2;
    const int qd  = lane & 3;

    const int row_s = tid >> 1;
    const int kh    = (tid & 1) * 16;
    const size_t agbase = (size_t)(bm + row_s) * HID + kh;
    const size_t bgbase = (size_t)(bn + row_s) * HID + kh;

    float acc[2][8][4];
    #pragma unroll
    for (int mt = 0; mt < 2; mt++)
        #pragma unroll
        for (int nt = 0; nt < 8; nt++)
            #pragma unroll
            for (int c = 0; c < 4; c++) acc[mt][nt][c] = 0.f;

    uint4 pa0 = *(const uint4*)(Ahi + agbase);
    uint4 pa1 = *(const uint4*)(Ahi + agbase + 8);
    uint4 pl0 = *(const uint4*)(Alo + agbase);
    uint4 pl1 = *(const uint4*)(Alo + agbase + 8);
    uint4 pb0 = *(const uint4*)(Bhi + bgbase);
    uint4 pb1 = *(const uint4*)(Bhi + bgbase + 8);
    uint4 pc0 = *(const uint4*)(Blo + bgbase);
    uint4 pc1 = *(const uint4*)(Blo + bgbase + 8);

    const int NKB = HID / 32;
    for (int kb = 0; kb < NKB; kb++) {
        *(uint4*)&sAhi[row_s][kh]     = pa0;
        *(uint4*)&sAhi[row_s][kh + 8] = pa1;
        *(uint4*)&sAlo[row_s][kh]     = pl0;
        *(uint4*)&sAlo[row_s][kh + 8] = pl1;
        *(uint4*)&sBhi[row_s][kh]     = pb0;
        *(uint4*)&sBhi[row_s][kh + 8] = pb1;
        *(uint4*)&sBlo[row_s][kh]     = pc0;
        *(uint4*)&sBlo[row_s][kh + 8] = pc1;
        __syncthreads();

        if (kb + 1 < NKB) {
            const size_t ao = agbase + (size_t)(kb + 1) * 32;
            const size_t bo = bgbase + (size_t)(kb + 1) * 32;
            pa0 = *(const uint4*)(Ahi + ao);
            pa1 = *(const uint4*)(Ahi + ao + 8);
            pl0 = *(const uint4*)(Alo + ao);
            pl1 = *(const uint4*)(Alo + ao + 8);
            pb0 = *(const uint4*)(Bhi + bo);
            pb1 = *(const uint4*)(Bhi + bo + 8);
            pc0 = *(const uint4*)(Blo + bo);
            pc1 = *(const uint4*)(Blo + bo + 8);
        }

        #pragma unroll
        for (int ks = 0; ks < 2; ks++) {
            const int kk = ks * 16 + qd * 2;
            u32 fahi[2][4], falo[2][4];
            #pragma unroll
            for (int mt = 0; mt < 2; mt++) {
                const int r0 = wm * 32 + mt * 16 + grp;
                const int r1 = r0 + 8;
                fahi[mt][0] = *(const u32*)&sAhi[r0][kk];
                fahi[mt][1] = *(const u32*)&sAhi[r1][kk];
                fahi[mt][2] = *(const u32*)&sAhi[r0][kk + 8];
                fahi[mt][3] = *(const u32*)&sAhi[r1][kk + 8];
                falo[mt][0] = *(const u32*)&sAlo[r0][kk];
                falo[mt][1] = *(const u32*)&sAlo[r1][kk];
                falo[mt][2] = *(const u32*)&sAlo[r0][kk + 8];
                falo[mt][3] = *(const u32*)&sAlo[r1][kk + 8];
            }
            #pragma unroll
            for (int nt = 0; nt < 8; nt++) {
                const int bc = wn * 64 + nt * 8 + grp;
                u32 bh0 = *(const u32*)&sBhi[bc][kk];
                u32 bh1 = *(const u32*)&sBhi[bc][kk + 8];
                u32 bl0 = *(const u32*)&sBlo[bc][kk];
                u32 bl1 = *(const u32*)&sBlo[bc][kk + 8];
                #pragma unroll
                for (int mt = 0; mt < 2; mt++) {
                    mma16816(acc[mt][nt], fahi[mt], bh0, bh1);
                    mma16816(acc[mt][nt], fahi[mt], bl0, bl1);
                    mma16816(acc[mt][nt], falo[mt], bh0, bh1);
                }
            }
        }
        __syncthreads();
    }

    #pragma unroll
    for (int mt = 0; mt < 2; mt++) {
        #pragma unroll
        for (int nt = 0; nt < 8; nt++) {
            const int r0 = bm + wm * 32 + mt * 16 + grp;
            const int cb = bn + wn * 64 + nt * 8 + qd * 2;
            float v00 = acc[mt][nt][0], v01 = acc[mt][nt][1];
            float v10 = acc[mt][nt][2], v11 = acc[mt][nt][3];
            if (Bias) {
                float b0 = Bias[cb], b1 = Bias[cb + 1];
                v00 += b0; v01 += b1; v10 += b0; v11 += b1;
            }
            *(float2*)(Out + (size_t)r0 * HID + cb)       = make_float2(v00, v01);
            *(float2*)(Out + (size_t)(r0 + 8) * HID + cb) = make_float2(v10, v11);
        }
    }
}

// ---------------------------------------------------------------------------
// q core (device fn): bit-exact FFMA2 GEMM, 128x128 tile, BK=16, 8x8/thread.
// Conflict-free B layout: [BK][2][16] float4 blocks; block j holds cols
// j*64 + t*4..+3. Thread tx owns cols {4tx, 64+4tx} (+0..3).
// ---------------------------------------------------------------------------
#define QBKD 16

__device__ __forceinline__
void q_core(char* smraw,
            const float* __restrict__ X, const float* __restrict__ Wq,
            const float* __restrict__ Bq, int bm, int bn) {
    typedef float ATile[QBKD][128];
    typedef float4 BTile2[QBKD][2][16];
    ATile* As = (ATile*)smraw;                        // [2] x 8KB
    BTile2* Bs = (BTile2*)(smraw + 16384);            // [2] x 8KB

    const int tid = threadIdx.x;
    const int tx  = tid & 15;
    const int ty  = tid >> 4;

    const int arow  = tid >> 1;
    const int akcol = (tid & 1) * 4;
    const int bkrow = tid >> 4;       // 0..15
    const int bc4   = tid & 15;       // float4 col group

    const float* Aptr = X + (size_t)(bm + arow) * HID + akcol;
    const float* Wp0  = Wq + (size_t)bkrow * HID + bn + bc4 * 4;
    const float* Wp1  = Wp0 + 64;

    u64 acc2[8][4];
    #pragma unroll
    for (int i = 0; i < 8; i++)
        #pragma unroll
        for (int j = 0; j < 4; j++) acc2[i][j] = 0ull;

    {
        float4 a0 = *(const float4*)(Aptr);
        float4 a1 = *(const float4*)(Aptr + 8);
        float4 b0 = *(const float4*)(Wp0);
        float4 b1 = *(const float4*)(Wp1);
        As[0][akcol + 0][arow] = a0.x; As[0][akcol + 1][arow] = a0.y;
        As[0][akcol + 2][arow] = a0.z; As[0][akcol + 3][arow] = a0.w;
        As[0][akcol + 8][arow] = a1.x; As[0][akcol + 9][arow] = a1.y;
        As[0][akcol +10][arow] = a1.z; As[0][akcol +11][arow] = a1.w;
        Bs[0][bkrow][0][bc4] = b0;
        Bs[0][bkrow][1][bc4] = b1;
    }
    __syncthreads();

    int cur = 0;
    for (int k0 = QBKD; k0 <= HID; k0 += QBKD) {
        float4 a0, a1, b0, b1;
        const bool more = (k0 < HID);
        if (more) {
            a0 = *(const float4*)(Aptr + k0);
            a1 = *(const float4*)(Aptr + k0 + 8);
            b0 = *(const float4*)(Wp0 + (size_t)k0 * HID);
            b1 = *(const float4*)(Wp1 + (size_t)k0 * HID);
        }

        #pragma unroll
        for (int kk = 0; kk < QBKD; kk++) {
            ulonglong2 q0 = *(const ulonglong2*)&Bs[cur][kk][0][tx];
            ulonglong2 q1 = *(const ulonglong2*)&Bs[cur][kk][1][tx];
            float4 av0 = *(const float4*)&As[cur][kk][ty * 8];
            float4 av1 = *(const float4*)&As[cur][kk][ty * 8 + 4];
            float a[8] = {av0.x, av0.y, av0.z, av0.w, av1.x, av1.y, av1.z, av1.w};
            #pragma unroll
            for (int i = 0; i < 8; i++) {
                u64 ap = pack_dup(a[i]);
                ffma2(acc2[i][0], ap, q0.x);
                ffma2(acc2[i][1], ap, q0.y);
                ffma2(acc2[i][2], ap, q1.x);
                ffma2(acc2[i][3], ap, q1.y);
            }
        }

        if (more) {
            const int nxt = cur ^ 1;
            As[nxt][akcol + 0][arow] = a0.x; As[nxt][akcol + 1][arow] = a0.y;
            As[nxt][akcol + 2][arow] = a0.z; As[nxt][akcol + 3][arow] = a0.w;
            As[nxt][akcol + 8][arow] = a1.x; As[nxt][akcol + 9][arow] = a1.y;
            As[nxt][akcol +10][arow] = a1.z; As[nxt][akcol +11][arow] = a1.w;
            Bs[nxt][bkrow][0][bc4] = b0;
            Bs[nxt][bkrow][1][bc4] = b1;
            __syncthreads();
            cur = nxt;
        }
    }

    // epilogue: acc2[i][0..1] -> cols bn+4tx..; acc2[i][2..3] -> bn+64+4tx..
    float4 bv0 = *(const float4*)(Bq + bn + 4 * tx);
    float4 bv1 = *(const float4*)(Bq + bn + 64 + 4 * tx);
    #pragma unroll
    for (int i = 0; i < 8; i++) {
        float* orow = g_q + (size_t)(bm + ty * 8 + i) * HID;
        float r0, r1, r2, r3;
        unpack2(acc2[i][0], r0, r1);
        unpack2(acc2[i][1], r2, r3);
        *(float4*)(orow + bn + 4 * tx) =
            make_float4(r0 + bv0.x, r1 + bv0.y, r2 + bv0.z, r3 + bv0.w);
        unpack2(acc2[i][2], r0, r1);
        unpack2(acc2[i][3], r2, r3);
        *(float4*)(orow + bn + 64 + 4 * tx) =
            make_float4(r0 + bv1.x, r1 + bv1.y, r2 + bv1.z, r3 + bv1.w);
    }
}

// ---------------------------------------------------------------------------
// MEGA kernel: heterogeneous blocks. bidx%3: 0 = q (FFMA2), 1 = k (mma),
// 2 = v (mma). Two blocks/SM (<=128 regs) -> fma + tensor pipes overlap.
// ---------------------------------------------------------------------------
__global__ __launch_bounds__(256, 2)
void mega_kernel(const float* __restrict__ X,
                 const float* __restrict__ Wq, const float* __restrict__ Bq,
                 const float* __restrict__ Bk, const float* __restrict__ Bv) {
    __shared__ __align__(16) char sm[SM_BYTES];
    const int bidx = blockIdx.x;
    const int type = bidx % 3;
    const int sub  = bidx / 3;          // 0..1023
    const int bm = (sub >> 3) * 128;
    const int bn = (sub & 7) * 128;

    if (type == 0) {
        q_core(sm, X, Wq, Bq, bm, bn);
    } else if (type == 1) {
        mma_core(sm, g_Wkhi, g_Wklo, g_k, Bk, bm, bn);
    } else {
        mma_core(sm, g_Wvhi, g_Wvlo, g_v, Bv, bm, bn);
    }
}

// Standalone mma kernel for the out GEMM (after den scaling)
__global__ __launch_bounds__(256)
void mma_out_kernel(float* __restrict__ Out) {
    __shared__ __align__(16) char sm[SM_BYTES];
    const int bm = blockIdx.x * 128;
    const int bn = blockIdx.y * 128;
    mma_core(sm, g_W2hi, g_W2lo, Out, (const float*)0, bm, bn);
}

// ---------------------------------------------------------------------------
// den + scale: strict sequential d=0..63 fmaf chain (reference rounding order)
// ---------------------------------------------------------------------------
__global__ __launch_bounds__(256, 4)
void den_scale_kernel(const float* __restrict__ Z) {
    __shared__ float tile[64][65];
    __shared__ float zsh[64];
    __shared__ float inv[64];

    const int h   = blockIdx.y;
    const int r0  = blockIdx.x * 64;
    const int tid = threadIdx.x;
    const size_t base = (size_t)r0 * HID + h * 64;

    if (tid < 64) zsh[tid] = Z[h * 64 + tid];

    #pragma unroll
    for (int t = 0; t < 4; t++) {
        int idx = tid + t * 256;
        int r   = idx >> 4;
        int c4  = (idx & 15) * 4;
        float4 v = *(const float4*)(g_q + base + (size_t)r * HID + c4);
        tile[r][c4 + 0] = v.x; tile[r][c4 + 1] = v.y;
        tile[r][c4 + 2] = v.z; tile[r][c4 + 3] = v.w;
    }
    __syncthreads();

    if (tid < 64) {
        float s = 0.f;
        for (int d = 0; d < 64; d++)
            s = fmaf(tile[tid][d], zsh[d], s);
        inv[tid] = 1.f / (fabsf(s) + 1e-6f);
    }
    __syncthreads();

    #pragma unroll
    for (int t = 0; t < 4; t++) {
        int idx = tid + t * 256;
        int r   = idx >> 4;
        int c4  = (idx & 15) * 4;
        float iv = inv[r];
        float4 v;
        v.x = tile[r][c4 + 0] * iv; v.y = tile[r][c4 + 1] * iv;
        v.z = tile[r][c4 + 2] * iv; v.w = tile[r][c4 + 3] * iv;
        *(float4*)(g_q + base + (size_t)r * HID + c4) = v;
    }
}

// ---------------------------------------------------------------------------
// state update: split-S partials (deterministic), then reduce
// ---------------------------------------------------------------------------
#define TS 16

__global__ __launch_bounds__(256, 4)
void update_state_kernel() {
    __shared__ float ks[TS][64];
    __shared__ float vs[TS][64];

    const int h      = blockIdx.y;
    const int chunk  = blockIdx.x;
    const int rows   = MROWS / NCHUNK;
    const int s_base = chunk * rows;

    const int tid = threadIdx.x;
    const int tx  = tid & 15;
    const int ty  = tid >> 4;
    const int s_l = tid >> 4;
    const int c4  = (tid & 15) * 4;

    float acc[4][4];
    #pragma unroll
    for (int i = 0; i < 4; i++)
        #pragma unroll
        for (int j = 0; j < 4; j++) acc[i][j] = 0.f;
    float zacc[4] = {0.f, 0.f, 0.f, 0.f};

    const size_t colbase = (size_t)h * 64 + c4;

    for (int s0 = s_base; s0 < s_base + rows; s0 += TS) {
        *(float4*)&ks[s_l][c4] = *(const float4*)(g_k + (size_t)(s0 + s_l) * HID + colbase);
        *(float4*)&vs[s_l][c4] = *(const float4*)(g_v + (size_t)(s0 + s_l) * HID + colbase);
        __syncthreads();

        #pragma unroll
        for (int s = 0; s < TS; s++) {
            float4 af = *(const float4*)&ks[s][ty * 4];
            float4 bf = *(const float4*)&vs[s][tx * 4];
            float a[4] = {af.x, af.y, af.z, af.w};
            float b[4] = {bf.x, bf.y, bf.z, bf.w};
            #pragma unroll
            for (int i = 0; i < 4; i++)
                #pragma unroll
                for (int j = 0; j < 4; j++)
                    acc[i][j] = fmaf(a[i], b[j], acc[i][j]);
            if (tx == 0) {
                #pragma unroll
                for (int i = 0; i < 4; i++) zacc[i] += a[i];
            }
        }
        __syncthreads();
    }

    float* mp = g_Mpart + (size_t)(chunk * NH + h) * 4096;
    #pragma unroll
    for (int i = 0; i < 4; i++)
        #pragma unroll
        for (int j = 0; j < 4; j++)
            mp[(ty * 4 + i) * 64 + tx * 4 + j] = acc[i][j];
    if (tx == 0) {
        #pragma unroll
        for (int i = 0; i < 4; i++)
            g_zpart[(size_t)chunk * Z_ELEMS + h * 64 + ty * 4 + i] = zacc[i];
    }
}

__global__ void reduce_state_kernel(const float* __restrict__ M,
                                    const float* __restrict__ z,
                                    float* __restrict__ outM,
                                    float* __restrict__ outz) {
    int i = blockIdx.x * 256 + threadIdx.x;
    if (i < M_ELEMS) {
        int h = i >> 12;
        int r = i & 4095;
        float s = M[i];
        for (int c = 0; c < NCHUNK; c++)
            s += g_Mpart[(size_t)(c * NH + h) * 4096 + r];
        outM[i] = s;
    }
    if (i < Z_ELEMS) {
        float s = z[i];
        for (int c = 0; c < NCHUNK; c++)
            s += g_zpart[(size_t)c * Z_ELEMS + i];
        outz[i] = s;
    }
}

// ---------------------------------------------------------------------------
// Launch
// ---------------------------------------------------------------------------
extern "C" void kernel_launch(void* const* d_in, const int* in_sizes, int n_in,
                              void* d_out, int out_size) {
    const float* X  = (const float*)d_in[0];
    const float* M  = (const float*)d_in[1];
    const float* z  = (const float*)d_in[2];
    const float* Wq = (const float*)d_in[3];
    const float* bq = (const float*)d_in[4];
    const float* Wk = (const float*)d_in[5];
    const float* bk = (const float*)d_in[6];
    const float* Wv = (const float*)d_in[7];
    const float* bv = (const float*)d_in[8];
    const float* Wo = (const float*)d_in[9];

    float* out  = (float*)d_out;
    float* outM = out + OUT_ELEMS;
    float* outz = out + OUT_ELEMS + M_ELEMS;

    // 1. W2 = blockdiag(M) @ Wo (fp32)
    build_w2_kernel<<<dim3(16, 16), 256>>>(M, Wo);
    // 2. weight conversions (transpose + bf16 split)
    conv_w_kernel<<<dim3(32, 32), 256>>>(Wk, 0);
    conv_w_kernel<<<dim3(32, 32), 256>>>(Wv, 1);
    conv_w_kernel<<<dim3(32, 32), 256>>>((const float*)0, 2);   // g_W2
    // 3. X -> bf16 split
    split_kernel<<<OUT_ELEMS / 4 / 256, 256>>>(X);
    // 4. MEGA: q (FFMA2, bit-exact) + k + v (tensor) concurrently
    mega_kernel<<<3072, 256>>>(X, Wq, bq, bk, bv);
    // 5. den (strict order) + scale q in place
    den_scale_kernel<<<dim3(MROWS / 64, NH), 256>>>(z);
    // 6. q/den -> bf16 split
    split_kernel<<<OUT_ELEMS / 4 / 256, 256>>>((const float*)0);
    // 7. out = (q/den) @ W2 (tensor)
    mma_out_kernel<<<dim3(MROWS / 128, HID / 128), 256>>>(out);
    // 8. state update
    update_state_kernel<<<dim3(NCHUNK, NH), 256>>>();
    reduce_state_kernel<<<256, 256>>>(M, z, outM, outz);
}